// round 13
// baseline (speedup 1.0000x reference)
#include <cuda_runtime.h>
#include <cuda_bf16.h>
#include <cuda_fp16.h>
#include <cstdint>
#include <math.h>

#define D 128
#define NMAX 100000
#define NPAD_MAX 100096

// ---- scratch (static device globals; no runtime allocation) ----
static __device__ float g_agg[(size_t)NMAX * D];                // scatter-sum of gathered rows
static __device__ __nv_bfloat16 g_Xhi[(size_t)NPAD_MAX * 256];  // X hi split
static __device__ __nv_bfloat16 g_Xlo[(size_t)NPAD_MAX * 256];  // X lo split
static __device__ __nv_bfloat16 g_B[512 * 768];                 // [n][ Bhi | Bhi | Blo ]
static __device__ __half g_C[(size_t)NPAD_MAX * 512];           // GEMM result (fp16 preacts)
static __device__ float g_bias[512];                            // br, bz, bxn, bhh_n

// ============================ PTX helpers (plain sm_103) ============================
__device__ __forceinline__ uint32_t smem_u32(const void* p) {
    uint32_t a;
    asm("{ .reg .u64 t; cvta.to.shared.u64 t, %1; cvt.u32.u64 %0, t; }" : "=r"(a) : "l"(p));
    return a;
}
__device__ __forceinline__ void cp_async16(uint32_t dst, const void* src) {
    asm volatile("cp.async.cg.shared.global [%0], [%1], 16;" :: "r"(dst), "l"(src));
}
__device__ __forceinline__ void ldm_x4(uint32_t* r, uint32_t addr) {
    asm volatile("ldmatrix.sync.aligned.m8n8.x4.shared.b16 {%0,%1,%2,%3}, [%4];"
                 : "=r"(r[0]), "=r"(r[1]), "=r"(r[2]), "=r"(r[3]) : "r"(addr));
}
__device__ __forceinline__ void mma_bf16(float* c, const uint32_t* a, uint32_t b0, uint32_t b1) {
    asm volatile(
        "mma.sync.aligned.m16n8k16.row.col.f32.bf16.bf16.f32 "
        "{%0,%1,%2,%3}, {%4,%5,%6,%7}, {%8,%9}, {%0,%1,%2,%3};"
        : "+f"(c[0]), "+f"(c[1]), "+f"(c[2]), "+f"(c[3])
        : "r"(a[0]), "r"(a[1]), "r"(a[2]), "r"(a[3]), "r"(b0), "r"(b1));
}
__device__ __forceinline__ float sigmoidf_(float x) { return 1.f / (1.f + expf(-x)); }
// load 4 consecutive fp16 preacts as fp32
__device__ __forceinline__ void ld4h(float* o, const uint2* p) {
    uint2 v = __ldg(p);
    const __half2* h = reinterpret_cast<const __half2*>(&v);
    float2 a = __half22float2(h[0]);
    float2 b = __half22float2(h[1]);
    o[0] = a.x; o[1] = a.y; o[2] = b.x; o[3] = b.y;
}

// ============================ zero ============================
__global__ void zero_kernel(int N) {
    size_t total = (size_t)N * 32;
    float4* p = reinterpret_cast<float4*>(g_agg);
    for (size_t i = blockIdx.x * (size_t)blockDim.x + threadIdx.x; i < total;
         i += (size_t)gridDim.x * blockDim.x)
        p[i] = make_float4(0.f, 0.f, 0.f, 0.f);
}

// ============================ scatter (4 edges/warp, direct ent gather) ============================
__global__ __launch_bounds__(256) void scatter_kernel(const float* __restrict__ ent,
                                                      const int* __restrict__ node_id,
                                                      const int* __restrict__ esrc,
                                                      const int* __restrict__ edst, int E) {
    int warp = (int)((blockIdx.x * (size_t)blockDim.x + threadIdx.x) >> 5);
    int lane = threadIdx.x & 31;
    int e0 = warp * 4;
    if (e0 >= E) return;
    int dst[4], row[4];
    #pragma unroll
    for (int j = 0; j < 4; j++) {
        if (e0 + j < E) {
            int s = __ldg(esrc + e0 + j);
            dst[j] = __ldg(edst + e0 + j);
            row[j] = __ldg(node_id + s);
        } else {
            dst[j] = -1; row[j] = 0;
        }
    }
    float4 v[4];
    #pragma unroll
    for (int j = 0; j < 4; j++)
        v[j] = __ldg(reinterpret_cast<const float4*>(ent) + (size_t)row[j] * 32 + lane);
    #pragma unroll
    for (int j = 0; j < 4; j++)
        if (dst[j] >= 0)
            atomicAdd(reinterpret_cast<float4*>(g_agg) + (size_t)dst[j] * 32 + lane, v[j]);
}

// ============================ build X (hi/lo bf16 split) + prep (merged) ==================
// Blocks [0, nbx): build_x. Blocks [nbx, nbx+513): weight prep (rides free under the
// DRAM-bound build_x stream). Both complete before the GEMM launch (stream order).
__global__ __launch_bounds__(256) void buildx_prep_kernel(
        const float* __restrict__ erb, const float* __restrict__ onorm,
        const float* __restrict__ W, const float* __restrict__ w_ih,
        const float* __restrict__ w_hh, const float* __restrict__ b_ih,
        const float* __restrict__ b_hh, int N, int npad, int nbx) {
    if ((int)blockIdx.x >= nbx) {
        // ---- prep part: folded B (bf16 hi/lo) + biases ----
        int n = blockIdx.x - nbx;   // 0..512
        int k = threadIdx.x;
        if (n == 512) {
            if (k < 128) {
                g_bias[k]       = b_ih[k] + b_hh[k];
                g_bias[128 + k] = b_ih[128 + k] + b_hh[128 + k];
                g_bias[256 + k] = b_ih[256 + k];
                g_bias[384 + k] = b_hh[256 + k];
            }
            return;
        }
        float v;
        if (k < 128) {
            if (n < 384) {
                float acc = 0.f;
                for (int j = 0; j < 128; j++) acc = fmaf(W[k * 128 + j], w_ih[n * 256 + j], acc);
                v = acc;
            } else v = 0.f;
        } else {
            if (n < 256)      v = w_ih[n * 256 + k] + w_hh[n * 128 + (k - 128)];
            else if (n < 384) v = w_ih[n * 256 + k];
            else              v = w_hh[(n - 128) * 128 + (k - 128)];
        }
        __nv_bfloat16 hi = __float2bfloat16_rn(v);
        __nv_bfloat16 lo = __float2bfloat16_rn(v - __bfloat162float(hi));
        g_B[n * 768 + k] = hi;
        g_B[n * 768 + 256 + k] = hi;
        g_B[n * 768 + 512 + k] = lo;
        return;
    }
    // ---- build_x part ----
    int i = blockIdx.x * blockDim.x + threadIdx.x;
    int node = i >> 5, lane = i & 31;
    if (node >= npad) return;
    float x[8];
    if (node < N) {
        float sc = __ldg(onorm + node);
        float4 a = __ldg(reinterpret_cast<const float4*>(g_agg) + (size_t)node * 32 + lane);
        float4 e = __ldg(reinterpret_cast<const float4*>(erb) + (size_t)node * 32 + lane);
        x[0] = a.x * sc; x[1] = a.y * sc; x[2] = a.z * sc; x[3] = a.w * sc;
        x[4] = e.x; x[5] = e.y; x[6] = e.z; x[7] = e.w;
    } else {
        #pragma unroll
        for (int q = 0; q < 8; q++) x[q] = 0.f;
    }
    unsigned short hs[8], ls[8];
    #pragma unroll
    for (int q = 0; q < 8; q++) {
        __nv_bfloat16 hb = __float2bfloat16_rn(x[q]);
        __nv_bfloat16 lb = __float2bfloat16_rn(x[q] - __bfloat162float(hb));
        hs[q] = *reinterpret_cast<unsigned short*>(&hb);
        ls[q] = *reinterpret_cast<unsigned short*>(&lb);
    }
    uint2* dhi0 = reinterpret_cast<uint2*>(g_Xhi + (size_t)node * 256 + lane * 4);
    uint2* dhi1 = reinterpret_cast<uint2*>(g_Xhi + (size_t)node * 256 + 128 + lane * 4);
    uint2* dlo0 = reinterpret_cast<uint2*>(g_Xlo + (size_t)node * 256 + lane * 4);
    uint2* dlo1 = reinterpret_cast<uint2*>(g_Xlo + (size_t)node * 256 + 128 + lane * 4);
    *dhi0 = make_uint2((uint32_t)hs[0] | ((uint32_t)hs[1] << 16), (uint32_t)hs[2] | ((uint32_t)hs[3] << 16));
    *dhi1 = make_uint2((uint32_t)hs[4] | ((uint32_t)hs[5] << 16), (uint32_t)hs[6] | ((uint32_t)hs[7] << 16));
    *dlo0 = make_uint2((uint32_t)ls[0] | ((uint32_t)ls[1] << 16), (uint32_t)ls[2] | ((uint32_t)ls[3] << 16));
    *dlo1 = make_uint2((uint32_t)ls[4] | ((uint32_t)ls[5] << 16), (uint32_t)ls[6] | ((uint32_t)ls[7] << 16));
}

// ============================ GEMM: C[npad,512] = Xv[npad,768] @ Bv[768,512]^T =========
// Virtual K chunks: 0-3 Xhi·Bhi, 4-7 Xlo·Bhi, 8-11 Xhi·Blo.
// hn gate (d0==384): B rows exactly 0 for k<128 → only chunks {2,3,6,7,10,11}.
// 3-stage cp.async pipeline, one barrier per stage. C stored as fp16.
#define STAGE_BYTES 32768
#define GEMM_SMEM (3 * STAGE_BYTES)

__global__ __launch_bounds__(256, 2) void gemm_kernel(int npad) {
    extern __shared__ char smc[];
    uint32_t sbase = smem_u32(smc);
    int tid = threadIdx.x, lane = tid & 31, w = tid >> 5;
    int n0 = blockIdx.x * 128;
    int d0 = blockIdx.y * 128;
    int wm = w & 3, wn = w >> 2;
    int m0 = wm * 32, nw0 = wn * 64;

    const int map3[6] = {2, 3, 6, 7, 10, 11};
    bool is_hn = (d0 == 384);
    int nch = is_hn ? 6 : 12;

    float acc[2][8][4];
    #pragma unroll
    for (int a = 0; a < 2; a++)
        #pragma unroll
        for (int b = 0; b < 8; b++)
            #pragma unroll
            for (int c = 0; c < 4; c++) acc[a][b][c] = 0.f;

    auto load_chunk = [&](int c, int st) {
        const __nv_bfloat16* X = (c >= 4 && c < 8) ? g_Xlo : g_Xhi;
        const __nv_bfloat16* Asrc = X + (size_t)n0 * 256 + (c & 3) * 64;
        const __nv_bfloat16* Bsrc = g_B + (size_t)d0 * 768 + c * 64;
        uint32_t abase = sbase + st * STAGE_BYTES;
        uint32_t bbase = abase + 16384;
        #pragma unroll
        for (int i = 0; i < 4; i++) {
            int e = i * 256 + tid;
            int row = e >> 3, ch = e & 7;
            cp_async16(abase + (row * 8 + (ch ^ (row & 7))) * 16,
                       Asrc + (size_t)row * 256 + ch * 8);
        }
        #pragma unroll
        for (int i = 0; i < 4; i++) {
            int e = i * 256 + tid;
            int row = e >> 3, ch = e & 7;
            cp_async16(bbase + (row * 8 + (ch ^ (row & 7))) * 16,
                       Bsrc + (size_t)row * 768 + ch * 8);
        }
        asm volatile("cp.async.commit_group;" ::: "memory");
    };

    auto chunk_of = [&](int i) { return is_hn ? map3[i] : i; };

    load_chunk(chunk_of(0), 0);
    load_chunk(chunk_of(1), 1);

    for (int i = 0; i < nch; i++) {
        int st = i % 3;
        if (i < nch - 1) asm volatile("cp.async.wait_group 1;" ::: "memory");
        else             asm volatile("cp.async.wait_group 0;" ::: "memory");
        __syncthreads();
        // safe: barrier above proves all warps finished reading stage (i+2)%3.
        if (i + 2 < nch) load_chunk(chunk_of(i + 2), (i + 2) % 3);
        uint32_t abase = sbase + st * STAGE_BYTES;
        uint32_t bbase = abase + 16384;
        #pragma unroll
        for (int k16 = 0; k16 < 4; k16++) {
            uint32_t af[2][4], bf[4][4];
            #pragma unroll
            for (int mi = 0; mi < 2; mi++) {
                int row = m0 + mi * 16 + (lane & 15);
                int ch = k16 * 2 + (lane >> 4);
                ldm_x4(af[mi], abase + (row * 8 + (ch ^ (row & 7))) * 16);
            }
            #pragma unroll
            for (int j = 0; j < 4; j++) {
                int row = nw0 + j * 16 + (lane & 15);
                int ch = k16 * 2 + (lane >> 4);
                ldm_x4(bf[j], bbase + (row * 8 + (ch ^ (row & 7))) * 16);
            }
            #pragma unroll
            for (int mi = 0; mi < 2; mi++)
                #pragma unroll
                for (int j = 0; j < 4; j++) {
                    mma_bf16(acc[mi][2 * j],     af[mi], bf[j][0], bf[j][2]);
                    mma_bf16(acc[mi][2 * j + 1], af[mi], bf[j][1], bf[j][3]);
                }
        }
    }

    int tr = lane >> 2, tc = (lane & 3) * 2;
    #pragma unroll
    for (int mi = 0; mi < 2; mi++) {
        #pragma unroll
        for (int j = 0; j < 8; j++) {
            int node = n0 + m0 + mi * 16 + tr;
            int d = d0 + nw0 + j * 8 + tc;
            float* cp = acc[mi][j];
            *reinterpret_cast<__half2*>(g_C + (size_t)node * 512 + d) =
                __floats2half2_rn(cp[0], cp[1]);
            *reinterpret_cast<__half2*>(g_C + (size_t)(node + 8) * 512 + d) =
                __floats2half2_rn(cp[2], cp[3]);
        }
    }
}

// ============================ epilogue: gates + relu + row norm ============================
__global__ __launch_bounds__(256) void epilogue_kernel(const float* __restrict__ erb,
                                                       float* __restrict__ out, int N) {
    int gw = (int)((blockIdx.x * (size_t)blockDim.x + threadIdx.x) >> 5);
    int lane = threadIdx.x & 31;
    if (gw >= N) return;
    const uint2* C2 = reinterpret_cast<const uint2*>(g_C + (size_t)gw * 512);
    float rr[4], zz[4], xx[4], hh[4];
    ld4h(rr, C2 + lane);          // gate r: halves [lane*4 .. lane*4+3]
    ld4h(zz, C2 + 32 + lane);     // gate z
    ld4h(xx, C2 + 64 + lane);     // gate xn
    ld4h(hh, C2 + 96 + lane);     // gate hn
    float4 e4 = __ldg(reinterpret_cast<const float4*>(erb) + (size_t)gw * 32 + lane);
    const float* ee = &e4.x;
    float hv[4];
    float ss = 0.f;
    #pragma unroll
    for (int i = 0; i < 4; i++) {
        int d = lane * 4 + i;
        float r = sigmoidf_(rr[i] + __ldg(g_bias + d));
        float z = sigmoidf_(zz[i] + __ldg(g_bias + 128 + d));
        float nn = tanhf(xx[i] + __ldg(g_bias + 256 + d) + r * (hh[i] + __ldg(g_bias + 384 + d)));
        float h = fmaxf((1.f - z) * nn + z * ee[i], 0.f);
        ss += h * h;
        hv[i] = h;
    }
    #pragma unroll
    for (int o = 16; o; o >>= 1) ss += __shfl_xor_sync(0xFFFFFFFFu, ss, o);
    float inv = 1.f / fmaxf(sqrtf(ss), 1e-12f);
    reinterpret_cast<float4*>(out)[(size_t)gw * 32 + lane] =
        make_float4(hv[0] * inv, hv[1] * inv, hv[2] * inv, hv[3] * inv);
}

// ============================ launch ============================
extern "C" void kernel_launch(void* const* d_in, const int* in_sizes, int n_in,
                              void* d_out, int out_size) {
    const float* ent   = (const float*)d_in[0];
    const float* erb   = (const float*)d_in[2];
    const float* onorm = (const float*)d_in[3];
    const float* Wn    = (const float*)d_in[4];
    const float* w_ih  = (const float*)d_in[5];
    const float* w_hh  = (const float*)d_in[6];
    const float* b_ih  = (const float*)d_in[7];
    const float* b_hh  = (const float*)d_in[8];
    const int* node_id = (const int*)d_in[9];
    const int* esrc    = (const int*)d_in[10];
    const int* edst    = (const int*)d_in[11];
    int N = in_sizes[3];
    int E = in_sizes[10];
    float* out = (float*)d_out;
    int npad = ((N + 127) / 128) * 128;
    if (npad > NPAD_MAX) npad = NPAD_MAX;

    cudaFuncSetAttribute(gemm_kernel, cudaFuncAttributeMaxDynamicSharedMemorySize, GEMM_SMEM);

    zero_kernel<<<512, 256>>>(N);

    int warps_needed = (E + 3) / 4;
    scatter_kernel<<<(warps_needed + 7) / 8, 256>>>(ent, node_id, esrc, edst, E);

    int nbx = (npad * 32 + 255) / 256;
    buildx_prep_kernel<<<nbx + 513, 256>>>(erb, onorm, Wn, w_ih, w_hh, b_ih, b_hh,
                                           N, npad, nbx);

    dim3 ggrid(npad / 128, 4);
    gemm_kernel<<<ggrid, 256, GEMM_SMEM>>>(npad);
    epilogue_kernel<<<(N * 32 + 255) / 256, 256>>>(erb, out, N);
}

// round 14
// speedup vs baseline: 1.0386x; 1.0386x over previous
#include <cuda_runtime.h>
#include <cuda_bf16.h>
#include <cuda_fp16.h>
#include <cstdint>
#include <math.h>

#define D 128
#define NMAX 100000
#define NPAD_MAX 100096

// ---- scratch (static device globals; no runtime allocation) ----
static __device__ float g_agg[(size_t)NMAX * D];                // scatter-sum of gathered rows
static __device__ __nv_bfloat16 g_Xhi[(size_t)NPAD_MAX * 256];  // X hi split
static __device__ __nv_bfloat16 g_Xlo[(size_t)NPAD_MAX * 256];  // X lo split
static __device__ __nv_bfloat16 g_B[512 * 768];                 // [n][ Bhi | Bhi | Blo ]
static __device__ __half g_C[(size_t)NPAD_MAX * 512];           // GEMM result (fp16 preacts)
static __device__ float g_bias[512];                            // br, bz, bxn, bhh_n

// ============================ PTX helpers (plain sm_103) ============================
__device__ __forceinline__ uint32_t smem_u32(const void* p) {
    uint32_t a;
    asm("{ .reg .u64 t; cvta.to.shared.u64 t, %1; cvt.u32.u64 %0, t; }" : "=r"(a) : "l"(p));
    return a;
}
__device__ __forceinline__ void cp_async16(uint32_t dst, const void* src) {
    asm volatile("cp.async.cg.shared.global [%0], [%1], 16;" :: "r"(dst), "l"(src));
}
__device__ __forceinline__ void ldm_x4(uint32_t* r, uint32_t addr) {
    asm volatile("ldmatrix.sync.aligned.m8n8.x4.shared.b16 {%0,%1,%2,%3}, [%4];"
                 : "=r"(r[0]), "=r"(r[1]), "=r"(r[2]), "=r"(r[3]) : "r"(addr));
}
__device__ __forceinline__ void mma_bf16(float* c, const uint32_t* a, uint32_t b0, uint32_t b1) {
    asm volatile(
        "mma.sync.aligned.m16n8k16.row.col.f32.bf16.bf16.f32 "
        "{%0,%1,%2,%3}, {%4,%5,%6,%7}, {%8,%9}, {%0,%1,%2,%3};"
        : "+f"(c[0]), "+f"(c[1]), "+f"(c[2]), "+f"(c[3])
        : "r"(a[0]), "r"(a[1]), "r"(a[2]), "r"(a[3]), "r"(b0), "r"(b1));
}
__device__ __forceinline__ float sigmoidf_(float x) { return 1.f / (1.f + expf(-x)); }
// load 4 consecutive fp16 preacts as fp32
__device__ __forceinline__ void ld4h(float* o, const uint2* p) {
    uint2 v = __ldg(p);
    const __half2* h = reinterpret_cast<const __half2*>(&v);
    float2 a = __half22float2(h[0]);
    float2 b = __half22float2(h[1]);
    o[0] = a.x; o[1] = a.y; o[2] = b.x; o[3] = b.y;
}

// ============================ prep: folded B (bf16 hi/lo) + biases ============================
__global__ void prep_kernel(const float* __restrict__ W, const float* __restrict__ w_ih,
                            const float* __restrict__ w_hh, const float* __restrict__ b_ih,
                            const float* __restrict__ b_hh) {
    int n = blockIdx.x;
    int k = threadIdx.x;
    if (n == 512) {
        if (k < 128) {
            g_bias[k]       = b_ih[k] + b_hh[k];
            g_bias[128 + k] = b_ih[128 + k] + b_hh[128 + k];
            g_bias[256 + k] = b_ih[256 + k];
            g_bias[384 + k] = b_hh[256 + k];
        }
        return;
    }
    float v;
    if (k < 128) {
        if (n < 384) {
            float acc = 0.f;
            for (int j = 0; j < 128; j++) acc = fmaf(W[k * 128 + j], w_ih[n * 256 + j], acc);
            v = acc;
        } else v = 0.f;
    } else {
        if (n < 256)      v = w_ih[n * 256 + k] + w_hh[n * 128 + (k - 128)];
        else if (n < 384) v = w_ih[n * 256 + k];
        else              v = w_hh[(n - 128) * 128 + (k - 128)];
    }
    __nv_bfloat16 hi = __float2bfloat16_rn(v);
    __nv_bfloat16 lo = __float2bfloat16_rn(v - __bfloat162float(hi));
    g_B[n * 768 + k] = hi;
    g_B[n * 768 + 256 + k] = hi;
    g_B[n * 768 + 512 + k] = lo;
}

// ============================ zero / scatter ============================
__global__ void zero_kernel(int N) {
    size_t total = (size_t)N * 32;
    float4* p = reinterpret_cast<float4*>(g_agg);
    for (size_t i = blockIdx.x * (size_t)blockDim.x + threadIdx.x; i < total;
         i += (size_t)gridDim.x * blockDim.x)
        p[i] = make_float4(0.f, 0.f, 0.f, 0.f);
}

// 4 edges per warp; reads ent rows directly via node_id indirection.
__global__ __launch_bounds__(256) void scatter_kernel(const float* __restrict__ ent,
                                                      const int* __restrict__ node_id,
                                                      const int* __restrict__ esrc,
                                                      const int* __restrict__ edst, int E) {
    int warp = (int)((blockIdx.x * (size_t)blockDim.x + threadIdx.x) >> 5);
    int lane = threadIdx.x & 31;
    int e0 = warp * 4;
    if (e0 >= E) return;
    int dst[4], row[4];
    #pragma unroll
    for (int j = 0; j < 4; j++) {
        if (e0 + j < E) {
            int s = __ldg(esrc + e0 + j);
            dst[j] = __ldg(edst + e0 + j);
            row[j] = __ldg(node_id + s);
        } else {
            dst[j] = -1; row[j] = 0;
        }
    }
    float4 v[4];
    #pragma unroll
    for (int j = 0; j < 4; j++)
        v[j] = __ldg(reinterpret_cast<const float4*>(ent) + (size_t)row[j] * 32 + lane);
    #pragma unroll
    for (int j = 0; j < 4; j++)
        if (dst[j] >= 0)
            atomicAdd(reinterpret_cast<float4*>(g_agg) + (size_t)dst[j] * 32 + lane, v[j]);
}

// ============================ build X (hi/lo bf16 split) ============================
__global__ __launch_bounds__(256) void build_x_kernel(const float* __restrict__ erb,
                                                      const float* __restrict__ onorm,
                                                      int N, int npad) {
    int i = blockIdx.x * blockDim.x + threadIdx.x;
    int node = i >> 5, lane = i & 31;
    if (node >= npad) return;
    float x[8];
    if (node < N) {
        float sc = __ldg(onorm + node);
        float4 a = __ldg(reinterpret_cast<const float4*>(g_agg) + (size_t)node * 32 + lane);
        float4 e = __ldg(reinterpret_cast<const float4*>(erb) + (size_t)node * 32 + lane);
        x[0] = a.x * sc; x[1] = a.y * sc; x[2] = a.z * sc; x[3] = a.w * sc;
        x[4] = e.x; x[5] = e.y; x[6] = e.z; x[7] = e.w;
    } else {
        #pragma unroll
        for (int q = 0; q < 8; q++) x[q] = 0.f;
    }
    unsigned short hs[8], ls[8];
    #pragma unroll
    for (int q = 0; q < 8; q++) {
        __nv_bfloat16 hb = __float2bfloat16_rn(x[q]);
        __nv_bfloat16 lb = __float2bfloat16_rn(x[q] - __bfloat162float(hb));
        hs[q] = *reinterpret_cast<unsigned short*>(&hb);
        ls[q] = *reinterpret_cast<unsigned short*>(&lb);
    }
    uint2* dhi0 = reinterpret_cast<uint2*>(g_Xhi + (size_t)node * 256 + lane * 4);
    uint2* dhi1 = reinterpret_cast<uint2*>(g_Xhi + (size_t)node * 256 + 128 + lane * 4);
    uint2* dlo0 = reinterpret_cast<uint2*>(g_Xlo + (size_t)node * 256 + lane * 4);
    uint2* dlo1 = reinterpret_cast<uint2*>(g_Xlo + (size_t)node * 256 + 128 + lane * 4);
    *dhi0 = make_uint2((uint32_t)hs[0] | ((uint32_t)hs[1] << 16), (uint32_t)hs[2] | ((uint32_t)hs[3] << 16));
    *dhi1 = make_uint2((uint32_t)hs[4] | ((uint32_t)hs[5] << 16), (uint32_t)hs[6] | ((uint32_t)hs[7] << 16));
    *dlo0 = make_uint2((uint32_t)ls[0] | ((uint32_t)ls[1] << 16), (uint32_t)ls[2] | ((uint32_t)ls[3] << 16));
    *dlo1 = make_uint2((uint32_t)ls[4] | ((uint32_t)ls[5] << 16), (uint32_t)ls[6] | ((uint32_t)ls[7] << 16));
}

// ============================ GEMM: C[npad,512] = Xv[npad,768] @ Bv[768,512]^T =========
// Virtual K chunks: 0-3 Xhi·Bhi, 4-7 Xlo·Bhi, 8-11 Xhi·Blo.
// hn gate (d0==384): B rows exactly 0 for k<128 → only chunks {2,3,6,7,10,11}.
// 4 warps/block, 64x64 warp tile (halves LDSM duplication: 96KB→64KB smem reads
// per chunk per block), 3-stage cp.async pipeline, C stored fp16.
#define STAGE_BYTES 32768
#define GEMM_SMEM (3 * STAGE_BYTES)

__global__ __launch_bounds__(128, 2) void gemm_kernel(int npad) {
    extern __shared__ char smc[];
    uint32_t sbase = smem_u32(smc);
    int tid = threadIdx.x, lane = tid & 31, w = tid >> 5;   // 4 warps
    int n0 = blockIdx.x * 128;
    int d0 = blockIdx.y * 128;
    int wm = w & 1, wn = w >> 1;
    int m0 = wm * 64, nw0 = wn * 64;

    const int map3[6] = {2, 3, 6, 7, 10, 11};
    bool is_hn = (d0 == 384);
    int nch = is_hn ? 6 : 12;

    float acc[4][8][4];   // 128 regs: 4 m16-frags x 8 n8-frags
    #pragma unroll
    for (int a = 0; a < 4; a++)
        #pragma unroll
        for (int b = 0; b < 8; b++)
            #pragma unroll
            for (int c = 0; c < 4; c++) acc[a][b][c] = 0.f;

    auto load_chunk = [&](int c, int st) {
        const __nv_bfloat16* X = (c >= 4 && c < 8) ? g_Xlo : g_Xhi;
        const __nv_bfloat16* Asrc = X + (size_t)n0 * 256 + (c & 3) * 64;
        const __nv_bfloat16* Bsrc = g_B + (size_t)d0 * 768 + c * 64;
        uint32_t abase = sbase + st * STAGE_BYTES;
        uint32_t bbase = abase + 16384;
        #pragma unroll
        for (int i = 0; i < 8; i++) {
            int e = i * 128 + tid;
            int row = e >> 3, ch = e & 7;
            cp_async16(abase + (row * 8 + (ch ^ (row & 7))) * 16,
                       Asrc + (size_t)row * 256 + ch * 8);
        }
        #pragma unroll
        for (int i = 0; i < 8; i++) {
            int e = i * 128 + tid;
            int row = e >> 3, ch = e & 7;
            cp_async16(bbase + (row * 8 + (ch ^ (row & 7))) * 16,
                       Bsrc + (size_t)row * 768 + ch * 8);
        }
        asm volatile("cp.async.commit_group;" ::: "memory");
    };

    auto chunk_of = [&](int i) { return is_hn ? map3[i] : i; };

    load_chunk(chunk_of(0), 0);
    load_chunk(chunk_of(1), 1);

    for (int i = 0; i < nch; i++) {
        int st = i % 3;
        if (i < nch - 1) asm volatile("cp.async.wait_group 1;" ::: "memory");
        else             asm volatile("cp.async.wait_group 0;" ::: "memory");
        __syncthreads();
        // safe: barrier above proves all warps finished reading stage (i+2)%3.
        if (i + 2 < nch) load_chunk(chunk_of(i + 2), (i + 2) % 3);
        uint32_t abase = sbase + st * STAGE_BYTES;
        uint32_t bbase = abase + 16384;
        #pragma unroll
        for (int k16 = 0; k16 < 4; k16++) {
            int ch = k16 * 2 + (lane >> 4);
            uint32_t af[4][4];
            #pragma unroll
            for (int mi = 0; mi < 4; mi++) {
                int row = m0 + mi * 16 + (lane & 15);
                ldm_x4(af[mi], abase + (row * 8 + (ch ^ (row & 7))) * 16);
            }
            #pragma unroll
            for (int j = 0; j < 4; j++) {
                uint32_t bf[4];
                int row = nw0 + j * 16 + (lane & 15);
                ldm_x4(bf, bbase + (row * 8 + (ch ^ (row & 7))) * 16);
                #pragma unroll
                for (int mi = 0; mi < 4; mi++) {
                    mma_bf16(acc[mi][2 * j],     af[mi], bf[0], bf[2]);
                    mma_bf16(acc[mi][2 * j + 1], af[mi], bf[1], bf[3]);
                }
            }
        }
    }

    int tr = lane >> 2, tc = (lane & 3) * 2;
    #pragma unroll
    for (int mi = 0; mi < 4; mi++) {
        #pragma unroll
        for (int j = 0; j < 8; j++) {
            int node = n0 + m0 + mi * 16 + tr;
            int d = d0 + nw0 + j * 8 + tc;
            float* cp = acc[mi][j];
            *reinterpret_cast<__half2*>(g_C + (size_t)node * 512 + d) =
                __floats2half2_rn(cp[0], cp[1]);
            *reinterpret_cast<__half2*>(g_C + (size_t)(node + 8) * 512 + d) =
                __floats2half2_rn(cp[2], cp[3]);
        }
    }
}

// ============================ epilogue: gates + relu + row norm ============================
__global__ __launch_bounds__(256) void epilogue_kernel(const float* __restrict__ erb,
                                                       float* __restrict__ out, int N) {
    int gw = (int)((blockIdx.x * (size_t)blockDim.x + threadIdx.x) >> 5);
    int lane = threadIdx.x & 31;
    if (gw >= N) return;
    const uint2* C2 = reinterpret_cast<const uint2*>(g_C + (size_t)gw * 512);
    float rr[4], zz[4], xx[4], hh[4];
    ld4h(rr, C2 + lane);          // gate r: halves [lane*4 .. lane*4+3]
    ld4h(zz, C2 + 32 + lane);     // gate z
    ld4h(xx, C2 + 64 + lane);     // gate xn
    ld4h(hh, C2 + 96 + lane);     // gate hn
    float4 e4 = __ldg(reinterpret_cast<const float4*>(erb) + (size_t)gw * 32 + lane);
    const float* ee = &e4.x;
    float hv[4];
    float ss = 0.f;
    #pragma unroll
    for (int i = 0; i < 4; i++) {
        int d = lane * 4 + i;
        float r = sigmoidf_(rr[i] + __ldg(g_bias + d));
        float z = sigmoidf_(zz[i] + __ldg(g_bias + 128 + d));
        float nn = tanhf(xx[i] + __ldg(g_bias + 256 + d) + r * (hh[i] + __ldg(g_bias + 384 + d)));
        float h = fmaxf((1.f - z) * nn + z * ee[i], 0.f);
        ss += h * h;
        hv[i] = h;
    }
    #pragma unroll
    for (int o = 16; o; o >>= 1) ss += __shfl_xor_sync(0xFFFFFFFFu, ss, o);
    float inv = 1.f / fmaxf(sqrtf(ss), 1e-12f);
    reinterpret_cast<float4*>(out)[(size_t)gw * 32 + lane] =
        make_float4(hv[0] * inv, hv[1] * inv, hv[2] * inv, hv[3] * inv);
}

// ============================ launch ============================
extern "C" void kernel_launch(void* const* d_in, const int* in_sizes, int n_in,
                              void* d_out, int out_size) {
    const float* ent   = (const float*)d_in[0];
    const float* erb   = (const float*)d_in[2];
    const float* onorm = (const float*)d_in[3];
    const float* Wn    = (const float*)d_in[4];
    const float* w_ih  = (const float*)d_in[5];
    const float* w_hh  = (const float*)d_in[6];
    const float* b_ih  = (const float*)d_in[7];
    const float* b_hh  = (const float*)d_in[8];
    const int* node_id = (const int*)d_in[9];
    const int* esrc    = (const int*)d_in[10];
    const int* edst    = (const int*)d_in[11];
    int N = in_sizes[3];
    int E = in_sizes[10];
    float* out = (float*)d_out;
    int npad = ((N + 127) / 128) * 128;
    if (npad > NPAD_MAX) npad = NPAD_MAX;

    cudaFuncSetAttribute(gemm_kernel, cudaFuncAttributeMaxDynamicSharedMemorySize, GEMM_SMEM);

    prep_kernel<<<513, 256>>>(Wn, w_ih, w_hh, b_ih, b_hh);
    zero_kernel<<<512, 256>>>(N);
    int warps_needed = (E + 3) / 4;
    scatter_kernel<<<(warps_needed + 7) / 8, 256>>>(ent, node_id, esrc, edst, E);
    build_x_kernel<<<(npad * 32 + 255) / 256, 256>>>(erb, onorm, N, npad);
    dim3 ggrid(npad / 128, 4);
    gemm_kernel<<<ggrid, 128, GEMM_SMEM>>>(npad);
    epilogue_kernel<<<(N * 32 + 255) / 256, 256>>>(erb, out, N);
}

// round 15
// speedup vs baseline: 1.0455x; 1.0067x over previous
#include <cuda_runtime.h>
#include <cuda_bf16.h>
#include <cuda_fp16.h>
#include <cstdint>
#include <math.h>

#define D 128
#define NMAX 100000
#define NPAD_MAX 100096

// ---- scratch (static device globals; no runtime allocation) ----
static __device__ float g_agg[(size_t)NMAX * D];                // scatter-sum of gathered rows
static __device__ __nv_bfloat16 g_Xhi[(size_t)NPAD_MAX * 256];  // X hi split
static __device__ __nv_bfloat16 g_Xlo[(size_t)NPAD_MAX * 256];  // X lo split
static __device__ __nv_bfloat16 g_B[512 * 768];                 // [n][ Bhi | Bhi | Blo ]
static __device__ __half g_C[(size_t)NPAD_MAX * 512];           // GEMM result (fp16 preacts)
static __device__ float g_bias[512];                            // br, bz, bxn, bhh_n

// ============================ PTX helpers (plain sm_103) ============================
__device__ __forceinline__ uint32_t smem_u32(const void* p) {
    uint32_t a;
    asm("{ .reg .u64 t; cvta.to.shared.u64 t, %1; cvt.u32.u64 %0, t; }" : "=r"(a) : "l"(p));
    return a;
}
__device__ __forceinline__ void cp_async16(uint32_t dst, const void* src) {
    asm volatile("cp.async.cg.shared.global [%0], [%1], 16;" :: "r"(dst), "l"(src));
}
__device__ __forceinline__ void ldm_x4(uint32_t* r, uint32_t addr) {
    asm volatile("ldmatrix.sync.aligned.m8n8.x4.shared.b16 {%0,%1,%2,%3}, [%4];"
                 : "=r"(r[0]), "=r"(r[1]), "=r"(r[2]), "=r"(r[3]) : "r"(addr));
}
__device__ __forceinline__ void mma_bf16(float* c, const uint32_t* a, uint32_t b0, uint32_t b1) {
    asm volatile(
        "mma.sync.aligned.m16n8k16.row.col.f32.bf16.bf16.f32 "
        "{%0,%1,%2,%3}, {%4,%5,%6,%7}, {%8,%9}, {%0,%1,%2,%3};"
        : "+f"(c[0]), "+f"(c[1]), "+f"(c[2]), "+f"(c[3])
        : "r"(a[0]), "r"(a[1]), "r"(a[2]), "r"(a[3]), "r"(b0), "r"(b1));
}
__device__ __forceinline__ float sigmoidf_(float x) { return 1.f / (1.f + expf(-x)); }
// load 4 consecutive fp16 preacts as fp32
__device__ __forceinline__ void ld4h(float* o, const uint2* p) {
    uint2 v = __ldg(p);
    const __half2* h = reinterpret_cast<const __half2*>(&v);
    float2 a = __half22float2(h[0]);
    float2 b = __half22float2(h[1]);
    o[0] = a.x; o[1] = a.y; o[2] = b.x; o[3] = b.y;
}

// ============================ prep + zero (merged; both independent, both precede scatter/gemm) ====
// Blocks [0,513): weight prep (compute-bound). Blocks [513, 1025): zero g_agg (DRAM-bound).
__global__ __launch_bounds__(256) void prep_zero_kernel(
        const float* __restrict__ W, const float* __restrict__ w_ih,
        const float* __restrict__ w_hh, const float* __restrict__ b_ih,
        const float* __restrict__ b_hh, int N) {
    if (blockIdx.x >= 513) {
        // ---- zero part: grid-stride over g_agg with 512 blocks ----
        size_t total = (size_t)N * 32;
        float4* p = reinterpret_cast<float4*>(g_agg);
        size_t base = ((size_t)blockIdx.x - 513) * blockDim.x + threadIdx.x;
        for (size_t i = base; i < total; i += (size_t)512 * blockDim.x)
            p[i] = make_float4(0.f, 0.f, 0.f, 0.f);
        return;
    }
    // ---- prep part: folded B (bf16 hi/lo) + biases ----
    int n = blockIdx.x;
    int k = threadIdx.x;
    if (n == 512) {
        if (k < 128) {
            g_bias[k]       = b_ih[k] + b_hh[k];
            g_bias[128 + k] = b_ih[128 + k] + b_hh[128 + k];
            g_bias[256 + k] = b_ih[256 + k];
            g_bias[384 + k] = b_hh[256 + k];
        }
        return;
    }
    float v;
    if (k < 128) {
        if (n < 384) {
            float acc = 0.f;
            for (int j = 0; j < 128; j++) acc = fmaf(W[k * 128 + j], w_ih[n * 256 + j], acc);
            v = acc;
        } else v = 0.f;
    } else {
        if (n < 256)      v = w_ih[n * 256 + k] + w_hh[n * 128 + (k - 128)];
        else if (n < 384) v = w_ih[n * 256 + k];
        else              v = w_hh[(n - 128) * 128 + (k - 128)];
    }
    __nv_bfloat16 hi = __float2bfloat16_rn(v);
    __nv_bfloat16 lo = __float2bfloat16_rn(v - __bfloat162float(hi));
    g_B[n * 768 + k] = hi;
    g_B[n * 768 + 256 + k] = hi;
    g_B[n * 768 + 512 + k] = lo;
}

// ============================ scatter (4 edges/warp, direct ent gather) ============================
__global__ __launch_bounds__(256) void scatter_kernel(const float* __restrict__ ent,
                                                      const int* __restrict__ node_id,
                                                      const int* __restrict__ esrc,
                                                      const int* __restrict__ edst, int E) {
    int warp = (int)((blockIdx.x * (size_t)blockDim.x + threadIdx.x) >> 5);
    int lane = threadIdx.x & 31;
    int e0 = warp * 4;
    if (e0 >= E) return;
    int dst[4], row[4];
    #pragma unroll
    for (int j = 0; j < 4; j++) {
        if (e0 + j < E) {
            int s = __ldg(esrc + e0 + j);
            dst[j] = __ldg(edst + e0 + j);
            row[j] = __ldg(node_id + s);
        } else {
            dst[j] = -1; row[j] = 0;
        }
    }
    float4 v[4];
    #pragma unroll
    for (int j = 0; j < 4; j++)
        v[j] = __ldg(reinterpret_cast<const float4*>(ent) + (size_t)row[j] * 32 + lane);
    #pragma unroll
    for (int j = 0; j < 4; j++)
        if (dst[j] >= 0)
            atomicAdd(reinterpret_cast<float4*>(g_agg) + (size_t)dst[j] * 32 + lane, v[j]);
}

// ============================ build X (hi/lo bf16 split) ============================
__global__ __launch_bounds__(256) void build_x_kernel(const float* __restrict__ erb,
                                                      const float* __restrict__ onorm,
                                                      int N, int npad) {
    int i = blockIdx.x * blockDim.x + threadIdx.x;
    int node = i >> 5, lane = i & 31;
    if (node >= npad) return;
    float x[8];
    if (node < N) {
        float sc = __ldg(onorm + node);
        float4 a = __ldg(reinterpret_cast<const float4*>(g_agg) + (size_t)node * 32 + lane);
        float4 e = __ldg(reinterpret_cast<const float4*>(erb) + (size_t)node * 32 + lane);
        x[0] = a.x * sc; x[1] = a.y * sc; x[2] = a.z * sc; x[3] = a.w * sc;
        x[4] = e.x; x[5] = e.y; x[6] = e.z; x[7] = e.w;
    } else {
        #pragma unroll
        for (int q = 0; q < 8; q++) x[q] = 0.f;
    }
    unsigned short hs[8], ls[8];
    #pragma unroll
    for (int q = 0; q < 8; q++) {
        __nv_bfloat16 hb = __float2bfloat16_rn(x[q]);
        __nv_bfloat16 lb = __float2bfloat16_rn(x[q] - __bfloat162float(hb));
        hs[q] = *reinterpret_cast<unsigned short*>(&hb);
        ls[q] = *reinterpret_cast<unsigned short*>(&lb);
    }
    uint2* dhi0 = reinterpret_cast<uint2*>(g_Xhi + (size_t)node * 256 + lane * 4);
    uint2* dhi1 = reinterpret_cast<uint2*>(g_Xhi + (size_t)node * 256 + 128 + lane * 4);
    uint2* dlo0 = reinterpret_cast<uint2*>(g_Xlo + (size_t)node * 256 + lane * 4);
    uint2* dlo1 = reinterpret_cast<uint2*>(g_Xlo + (size_t)node * 256 + 128 + lane * 4);
    *dhi0 = make_uint2((uint32_t)hs[0] | ((uint32_t)hs[1] << 16), (uint32_t)hs[2] | ((uint32_t)hs[3] << 16));
    *dhi1 = make_uint2((uint32_t)hs[4] | ((uint32_t)hs[5] << 16), (uint32_t)hs[6] | ((uint32_t)hs[7] << 16));
    *dlo0 = make_uint2((uint32_t)ls[0] | ((uint32_t)ls[1] << 16), (uint32_t)ls[2] | ((uint32_t)ls[3] << 16));
    *dlo1 = make_uint2((uint32_t)ls[4] | ((uint32_t)ls[5] << 16), (uint32_t)ls[6] | ((uint32_t)ls[7] << 16));
}

// ============================ GEMM: C[npad,512] = Xv[npad,768] @ Bv[768,512]^T =========
// Virtual K chunks: 0-3 Xhi·Bhi, 4-7 Xlo·Bhi, 8-11 Xhi·Blo.
// hn gate (d0==384): B rows exactly 0 for k<128 → only chunks {2,3,6,7,10,11}.
// 3-stage cp.async pipeline, one barrier per stage. C stored as fp16.
#define STAGE_BYTES 32768
#define GEMM_SMEM (3 * STAGE_BYTES)

__global__ __launch_bounds__(256, 2) void gemm_kernel(int npad) {
    extern __shared__ char smc[];
    uint32_t sbase = smem_u32(smc);
    int tid = threadIdx.x, lane = tid & 31, w = tid >> 5;
    int n0 = blockIdx.x * 128;
    int d0 = blockIdx.y * 128;
    int wm = w & 3, wn = w >> 2;
    int m0 = wm * 32, nw0 = wn * 64;

    const int map3[6] = {2, 3, 6, 7, 10, 11};
    bool is_hn = (d0 == 384);
    int nch = is_hn ? 6 : 12;

    float acc[2][8][4];
    #pragma unroll
    for (int a = 0; a < 2; a++)
        #pragma unroll
        for (int b = 0; b < 8; b++)
            #pragma unroll
            for (int c = 0; c < 4; c++) acc[a][b][c] = 0.f;

    auto load_chunk = [&](int c, int st) {
        const __nv_bfloat16* X = (c >= 4 && c < 8) ? g_Xlo : g_Xhi;
        const __nv_bfloat16* Asrc = X + (size_t)n0 * 256 + (c & 3) * 64;
        const __nv_bfloat16* Bsrc = g_B + (size_t)d0 * 768 + c * 64;
        uint32_t abase = sbase + st * STAGE_BYTES;
        uint32_t bbase = abase + 16384;
        #pragma unroll
        for (int i = 0; i < 4; i++) {
            int e = i * 256 + tid;
            int row = e >> 3, ch = e & 7;
            cp_async16(abase + (row * 8 + (ch ^ (row & 7))) * 16,
                       Asrc + (size_t)row * 256 + ch * 8);
        }
        #pragma unroll
        for (int i = 0; i < 4; i++) {
            int e = i * 256 + tid;
            int row = e >> 3, ch = e & 7;
            cp_async16(bbase + (row * 8 + (ch ^ (row & 7))) * 16,
                       Bsrc + (size_t)row * 768 + ch * 8);
        }
        asm volatile("cp.async.commit_group;" ::: "memory");
    };

    auto chunk_of = [&](int i) { return is_hn ? map3[i] : i; };

    load_chunk(chunk_of(0), 0);
    load_chunk(chunk_of(1), 1);

    for (int i = 0; i < nch; i++) {
        int st = i % 3;
        if (i < nch - 1) asm volatile("cp.async.wait_group 1;" ::: "memory");
        else             asm volatile("cp.async.wait_group 0;" ::: "memory");
        __syncthreads();
        // safe: barrier above proves all warps finished reading stage (i+2)%3.
        if (i + 2 < nch) load_chunk(chunk_of(i + 2), (i + 2) % 3);
        uint32_t abase = sbase + st * STAGE_BYTES;
        uint32_t bbase = abase + 16384;
        #pragma unroll
        for (int k16 = 0; k16 < 4; k16++) {
            uint32_t af[2][4], bf[4][4];
            #pragma unroll
            for (int mi = 0; mi < 2; mi++) {
                int row = m0 + mi * 16 + (lane & 15);
                int ch = k16 * 2 + (lane >> 4);
                ldm_x4(af[mi], abase + (row * 8 + (ch ^ (row & 7))) * 16);
            }
            #pragma unroll
            for (int j = 0; j < 4; j++) {
                int row = nw0 + j * 16 + (lane & 15);
                int ch = k16 * 2 + (lane >> 4);
                ldm_x4(bf[j], bbase + (row * 8 + (ch ^ (row & 7))) * 16);
            }
            #pragma unroll
            for (int mi = 0; mi < 2; mi++)
                #pragma unroll
                for (int j = 0; j < 4; j++) {
                    mma_bf16(acc[mi][2 * j],     af[mi], bf[j][0], bf[j][2]);
                    mma_bf16(acc[mi][2 * j + 1], af[mi], bf[j][1], bf[j][3]);
                }
        }
    }

    int tr = lane >> 2, tc = (lane & 3) * 2;
    #pragma unroll
    for (int mi = 0; mi < 2; mi++) {
        #pragma unroll
        for (int j = 0; j < 8; j++) {
            int node = n0 + m0 + mi * 16 + tr;
            int d = d0 + nw0 + j * 8 + tc;
            float* cp = acc[mi][j];
            *reinterpret_cast<__half2*>(g_C + (size_t)node * 512 + d) =
                __floats2half2_rn(cp[0], cp[1]);
            *reinterpret_cast<__half2*>(g_C + (size_t)(node + 8) * 512 + d) =
                __floats2half2_rn(cp[2], cp[3]);
        }
    }
}

// ============================ epilogue: gates + relu + row norm ============================
__global__ __launch_bounds__(256) void epilogue_kernel(const float* __restrict__ erb,
                                                       float* __restrict__ out, int N) {
    int gw = (int)((blockIdx.x * (size_t)blockDim.x + threadIdx.x) >> 5);
    int lane = threadIdx.x & 31;
    if (gw >= N) return;
    const uint2* C2 = reinterpret_cast<const uint2*>(g_C + (size_t)gw * 512);
    float rr[4], zz[4], xx[4], hh[4];
    ld4h(rr, C2 + lane);          // gate r: halves [lane*4 .. lane*4+3]
    ld4h(zz, C2 + 32 + lane);     // gate z
    ld4h(xx, C2 + 64 + lane);     // gate xn
    ld4h(hh, C2 + 96 + lane);     // gate hn
    float4 e4 = __ldg(reinterpret_cast<const float4*>(erb) + (size_t)gw * 32 + lane);
    const float* ee = &e4.x;
    float hv[4];
    float ss = 0.f;
    #pragma unroll
    for (int i = 0; i < 4; i++) {
        int d = lane * 4 + i;
        float r = sigmoidf_(rr[i] + __ldg(g_bias + d));
        float z = sigmoidf_(zz[i] + __ldg(g_bias + 128 + d));
        float nn = tanhf(xx[i] + __ldg(g_bias + 256 + d) + r * (hh[i] + __ldg(g_bias + 384 + d)));
        float h = fmaxf((1.f - z) * nn + z * ee[i], 0.f);
        ss += h * h;
        hv[i] = h;
    }
    #pragma unroll
    for (int o = 16; o; o >>= 1) ss += __shfl_xor_sync(0xFFFFFFFFu, ss, o);
    float inv = 1.f / fmaxf(sqrtf(ss), 1e-12f);
    reinterpret_cast<float4*>(out)[(size_t)gw * 32 + lane] =
        make_float4(hv[0] * inv, hv[1] * inv, hv[2] * inv, hv[3] * inv);
}

// ============================ launch ============================
extern "C" void kernel_launch(void* const* d_in, const int* in_sizes, int n_in,
                              void* d_out, int out_size) {
    const float* ent   = (const float*)d_in[0];
    const float* erb   = (const float*)d_in[2];
    const float* onorm = (const float*)d_in[3];
    const float* Wn    = (const float*)d_in[4];
    const float* w_ih  = (const float*)d_in[5];
    const float* w_hh  = (const float*)d_in[6];
    const float* b_ih  = (const float*)d_in[7];
    const float* b_hh  = (const float*)d_in[8];
    const int* node_id = (const int*)d_in[9];
    const int* esrc    = (const int*)d_in[10];
    const int* edst    = (const int*)d_in[11];
    int N = in_sizes[3];
    int E = in_sizes[10];
    float* out = (float*)d_out;
    int npad = ((N + 127) / 128) * 128;
    if (npad > NPAD_MAX) npad = NPAD_MAX;

    cudaFuncSetAttribute(gemm_kernel, cudaFuncAttributeMaxDynamicSharedMemorySize, GEMM_SMEM);

    prep_zero_kernel<<<1025, 256>>>(Wn, w_ih, w_hh, b_ih, b_hh, N);
    int warps_needed = (E + 3) / 4;
    scatter_kernel<<<(warps_needed + 7) / 8, 256>>>(ent, node_id, esrc, edst, E);
    build_x_kernel<<<(npad * 32 + 255) / 256, 256>>>(erb, onorm, N, npad);
    dim3 ggrid(npad / 128, 4);
    gemm_kernel<<<ggrid, 256, GEMM_SMEM>>>(npad);
    epilogue_kernel<<<(N * 32 + 255) / 256, 256>>>(erb, out, N);
}

// round 16
// speedup vs baseline: 1.2227x; 1.1695x over previous
#include <cuda_runtime.h>
#include <cuda_bf16.h>
#include <cuda_fp16.h>
#include <cstdint>
#include <math.h>

#define D 128
#define NMAX 100000
#define NPAD_MAX 100096

// ---- scratch (static device globals; no runtime allocation) ----
static __device__ float g_agg[(size_t)NMAX * D];                // scatter-sum of gathered rows
static __device__ __half g_X[(size_t)NPAD_MAX * 256];           // X (single fp16 term)
static __device__ __half g_B[512 * 512];                        // [n][ Bhi(256) | Blo(256) ] fp16
static __device__ __half g_C[(size_t)NPAD_MAX * 512];           // GEMM result (fp16 preacts)
static __device__ float g_bias[512];                            // br, bz, bxn, bhh_n

// ============================ PTX helpers (plain sm_103) ============================
__device__ __forceinline__ uint32_t smem_u32(const void* p) {
    uint32_t a;
    asm("{ .reg .u64 t; cvta.to.shared.u64 t, %1; cvt.u32.u64 %0, t; }" : "=r"(a) : "l"(p));
    return a;
}
__device__ __forceinline__ void cp_async16(uint32_t dst, const void* src) {
    asm volatile("cp.async.cg.shared.global [%0], [%1], 16;" :: "r"(dst), "l"(src));
}
__device__ __forceinline__ void ldm_x4(uint32_t* r, uint32_t addr) {
    asm volatile("ldmatrix.sync.aligned.m8n8.x4.shared.b16 {%0,%1,%2,%3}, [%4];"
                 : "=r"(r[0]), "=r"(r[1]), "=r"(r[2]), "=r"(r[3]) : "r"(addr));
}
__device__ __forceinline__ void mma_fp16(float* c, const uint32_t* a, uint32_t b0, uint32_t b1) {
    asm volatile(
        "mma.sync.aligned.m16n8k16.row.col.f32.f16.f16.f32 "
        "{%0,%1,%2,%3}, {%4,%5,%6,%7}, {%8,%9}, {%0,%1,%2,%3};"
        : "+f"(c[0]), "+f"(c[1]), "+f"(c[2]), "+f"(c[3])
        : "r"(a[0]), "r"(a[1]), "r"(a[2]), "r"(a[3]), "r"(b0), "r"(b1));
}
__device__ __forceinline__ float sigmoidf_(float x) { return 1.f / (1.f + expf(-x)); }
// load 4 consecutive fp16 preacts as fp32
__device__ __forceinline__ void ld4h(float* o, const uint2* p) {
    uint2 v = __ldg(p);
    const __half2* h = reinterpret_cast<const __half2*>(&v);
    float2 a = __half22float2(h[0]);
    float2 b = __half22float2(h[1]);
    o[0] = a.x; o[1] = a.y; o[2] = b.x; o[3] = b.y;
}

// ============================ prep + zero (merged) ============================
// Blocks [0,513): weight prep (compute-bound, fp16 hi/lo). Blocks [513,1025): zero g_agg.
__global__ __launch_bounds__(256) void prep_zero_kernel(
        const float* __restrict__ W, const float* __restrict__ w_ih,
        const float* __restrict__ w_hh, const float* __restrict__ b_ih,
        const float* __restrict__ b_hh, int N) {
    if (blockIdx.x >= 513) {
        size_t total = (size_t)N * 32;
        float4* p = reinterpret_cast<float4*>(g_agg);
        size_t base = ((size_t)blockIdx.x - 513) * blockDim.x + threadIdx.x;
        for (size_t i = base; i < total; i += (size_t)512 * blockDim.x)
            p[i] = make_float4(0.f, 0.f, 0.f, 0.f);
        return;
    }
    int n = blockIdx.x;
    int k = threadIdx.x;
    if (n == 512) {
        if (k < 128) {
            g_bias[k]       = b_ih[k] + b_hh[k];
            g_bias[128 + k] = b_ih[128 + k] + b_hh[128 + k];
            g_bias[256 + k] = b_ih[256 + k];
            g_bias[384 + k] = b_hh[256 + k];
        }
        return;
    }
    float v;
    if (k < 128) {
        if (n < 384) {
            float acc = 0.f;
            for (int j = 0; j < 128; j++) acc = fmaf(W[k * 128 + j], w_ih[n * 256 + j], acc);
            v = acc;
        } else v = 0.f;
    } else {
        if (n < 256)      v = w_ih[n * 256 + k] + w_hh[n * 128 + (k - 128)];
        else if (n < 384) v = w_ih[n * 256 + k];
        else              v = w_hh[(n - 128) * 128 + (k - 128)];
    }
    __half hi = __float2half_rn(v);
    __half lo = __float2half_rn(v - __half2float(hi));
    g_B[n * 512 + k] = hi;
    g_B[n * 512 + 256 + k] = lo;
}

// ============================ scatter (4 edges/warp, direct ent gather) ============================
__global__ __launch_bounds__(256) void scatter_kernel(const float* __restrict__ ent,
                                                      const int* __restrict__ node_id,
                                                      const int* __restrict__ esrc,
                                                      const int* __restrict__ edst, int E) {
    int warp = (int)((blockIdx.x * (size_t)blockDim.x + threadIdx.x) >> 5);
    int lane = threadIdx.x & 31;
    int e0 = warp * 4;
    if (e0 >= E) return;
    int dst[4], row[4];
    #pragma unroll
    for (int j = 0; j < 4; j++) {
        if (e0 + j < E) {
            int s = __ldg(esrc + e0 + j);
            dst[j] = __ldg(edst + e0 + j);
            row[j] = __ldg(node_id + s);
        } else {
            dst[j] = -1; row[j] = 0;
        }
    }
    float4 v[4];
    #pragma unroll
    for (int j = 0; j < 4; j++)
        v[j] = __ldg(reinterpret_cast<const float4*>(ent) + (size_t)row[j] * 32 + lane);
    #pragma unroll
    for (int j = 0; j < 4; j++)
        if (dst[j] >= 0)
            atomicAdd(reinterpret_cast<float4*>(g_agg) + (size_t)dst[j] * 32 + lane, v[j]);
}

// ============================ build X (single fp16) ============================
__global__ __launch_bounds__(256) void build_x_kernel(const float* __restrict__ erb,
                                                      const float* __restrict__ onorm,
                                                      int N, int npad) {
    int i = blockIdx.x * blockDim.x + threadIdx.x;
    int node = i >> 5, lane = i & 31;
    if (node >= npad) return;
    float x[8];
    if (node < N) {
        float sc = __ldg(onorm + node);
        float4 a = __ldg(reinterpret_cast<const float4*>(g_agg) + (size_t)node * 32 + lane);
        float4 e = __ldg(reinterpret_cast<const float4*>(erb) + (size_t)node * 32 + lane);
        x[0] = a.x * sc; x[1] = a.y * sc; x[2] = a.z * sc; x[3] = a.w * sc;
        x[4] = e.x; x[5] = e.y; x[6] = e.z; x[7] = e.w;
    } else {
        #pragma unroll
        for (int q = 0; q < 8; q++) x[q] = 0.f;
    }
    __half2 h01 = __floats2half2_rn(x[0], x[1]);
    __half2 h23 = __floats2half2_rn(x[2], x[3]);
    __half2 h45 = __floats2half2_rn(x[4], x[5]);
    __half2 h67 = __floats2half2_rn(x[6], x[7]);
    *reinterpret_cast<uint2*>(g_X + (size_t)node * 256 + lane * 4) =
        make_uint2(*reinterpret_cast<uint32_t*>(&h01), *reinterpret_cast<uint32_t*>(&h23));
    *reinterpret_cast<uint2*>(g_X + (size_t)node * 256 + 128 + lane * 4) =
        make_uint2(*reinterpret_cast<uint32_t*>(&h45), *reinterpret_cast<uint32_t*>(&h67));
}

// ============================ GEMM: C[npad,512] = Xv[npad,512] @ Bv[512,512]^T =========
// Virtual K chunks (fp16): 0-3 X·Bhi, 4-7 X·Blo.
// hn gate (d0==384): B rows exactly 0 for k<128 → only chunks {2,3,6,7}.
// 3-stage cp.async pipeline, one barrier per stage. C stored as fp16.
#define STAGE_BYTES 32768
#define GEMM_SMEM (3 * STAGE_BYTES)

__global__ __launch_bounds__(256, 2) void gemm_kernel(int npad) {
    extern __shared__ char smc[];
    uint32_t sbase = smem_u32(smc);
    int tid = threadIdx.x, lane = tid & 31, w = tid >> 5;
    int n0 = blockIdx.x * 128;
    int d0 = blockIdx.y * 128;
    int wm = w & 3, wn = w >> 2;
    int m0 = wm * 32, nw0 = wn * 64;

    const int map2[4] = {2, 3, 6, 7};
    bool is_hn = (d0 == 384);
    int nch = is_hn ? 4 : 8;

    float acc[2][8][4];
    #pragma unroll
    for (int a = 0; a < 2; a++)
        #pragma unroll
        for (int b = 0; b < 8; b++)
            #pragma unroll
            for (int c = 0; c < 4; c++) acc[a][b][c] = 0.f;

    auto load_chunk = [&](int c, int st) {
        const __half* Asrc = g_X + (size_t)n0 * 256 + (c & 3) * 64;
        const __half* Bsrc = g_B + (size_t)d0 * 512 + (c >> 2) * 256 + (c & 3) * 64;
        uint32_t abase = sbase + st * STAGE_BYTES;
        uint32_t bbase = abase + 16384;
        #pragma unroll
        for (int i = 0; i < 4; i++) {
            int e = i * 256 + tid;
            int row = e >> 3, ch = e & 7;
            cp_async16(abase + (row * 8 + (ch ^ (row & 7))) * 16,
                       Asrc + (size_t)row * 256 + ch * 8);
        }
        #pragma unroll
        for (int i = 0; i < 4; i++) {
            int e = i * 256 + tid;
            int row = e >> 3, ch = e & 7;
            cp_async16(bbase + (row * 8 + (ch ^ (row & 7))) * 16,
                       Bsrc + (size_t)row * 512 + ch * 8);
        }
        asm volatile("cp.async.commit_group;" ::: "memory");
    };

    auto chunk_of = [&](int i) { return is_hn ? map2[i] : i; };

    load_chunk(chunk_of(0), 0);
    load_chunk(chunk_of(1), 1);

    for (int i = 0; i < nch; i++) {
        int st = i % 3;
        if (i < nch - 1) asm volatile("cp.async.wait_group 1;" ::: "memory");
        else             asm volatile("cp.async.wait_group 0;" ::: "memory");
        __syncthreads();
        // safe: barrier above proves all warps finished reading stage (i+2)%3.
        if (i + 2 < nch) load_chunk(chunk_of(i + 2), (i + 2) % 3);
        uint32_t abase = sbase + st * STAGE_BYTES;
        uint32_t bbase = abase + 16384;
        #pragma unroll
        for (int k16 = 0; k16 < 4; k16++) {
            uint32_t af[2][4], bf[4][4];
            #pragma unroll
            for (int mi = 0; mi < 2; mi++) {
                int row = m0 + mi * 16 + (lane & 15);
                int ch = k16 * 2 + (lane >> 4);
                ldm_x4(af[mi], abase + (row * 8 + (ch ^ (row & 7))) * 16);
            }
            #pragma unroll
            for (int j = 0; j < 4; j++) {
                int row = nw0 + j * 16 + (lane & 15);
                int ch = k16 * 2 + (lane >> 4);
                ldm_x4(bf[j], bbase + (row * 8 + (ch ^ (row & 7))) * 16);
            }
            #pragma unroll
            for (int mi = 0; mi < 2; mi++)
                #pragma unroll
                for (int j = 0; j < 4; j++) {
                    mma_fp16(acc[mi][2 * j],     af[mi], bf[j][0], bf[j][2]);
                    mma_fp16(acc[mi][2 * j + 1], af[mi], bf[j][1], bf[j][3]);
                }
        }
    }

    int tr = lane >> 2, tc = (lane & 3) * 2;
    #pragma unroll
    for (int mi = 0; mi < 2; mi++) {
        #pragma unroll
        for (int j = 0; j < 8; j++) {
            int node = n0 + m0 + mi * 16 + tr;
            int d = d0 + nw0 + j * 8 + tc;
            float* cp = acc[mi][j];
            *reinterpret_cast<__half2*>(g_C + (size_t)node * 512 + d) =
                __floats2half2_rn(cp[0], cp[1]);
            *reinterpret_cast<__half2*>(g_C + (size_t)(node + 8) * 512 + d) =
                __floats2half2_rn(cp[2], cp[3]);
        }
    }
}

// ============================ epilogue: gates + relu + row norm ============================
__global__ __launch_bounds__(256) void epilogue_kernel(const float* __restrict__ erb,
                                                       float* __restrict__ out, int N) {
    int gw = (int)((blockIdx.x * (size_t)blockDim.x + threadIdx.x) >> 5);
    int lane = threadIdx.x & 31;
    if (gw >= N) return;
    const uint2* C2 = reinterpret_cast<const uint2*>(g_C + (size_t)gw * 512);
    float rr[4], zz[4], xx[4], hh[4];
    ld4h(rr, C2 + lane);          // gate r: halves [lane*4 .. lane*4+3]
    ld4h(zz, C2 + 32 + lane);     // gate z
    ld4h(xx, C2 + 64 + lane);     // gate xn
    ld4h(hh, C2 + 96 + lane);     // gate hn
    float4 e4 = __ldg(reinterpret_cast<const float4*>(erb) + (size_t)gw * 32 + lane);
    const float* ee = &e4.x;
    float hv[4];
    float ss = 0.f;
    #pragma unroll
    for (int i = 0; i < 4; i++) {
        int d = lane * 4 + i;
        float r = sigmoidf_(rr[i] + __ldg(g_bias + d));
        float z = sigmoidf_(zz[i] + __ldg(g_bias + 128 + d));
        float nn = tanhf(xx[i] + __ldg(g_bias + 256 + d) + r * (hh[i] + __ldg(g_bias + 384 + d)));
        float h = fmaxf((1.f - z) * nn + z * ee[i], 0.f);
        ss += h * h;
        hv[i] = h;
    }
    #pragma unroll
    for (int o = 16; o; o >>= 1) ss += __shfl_xor_sync(0xFFFFFFFFu, ss, o);
    float inv = 1.f / fmaxf(sqrtf(ss), 1e-12f);
    reinterpret_cast<float4*>(out)[(size_t)gw * 32 + lane] =
        make_float4(hv[0] * inv, hv[1] * inv, hv[2] * inv, hv[3] * inv);
}

// ============================ launch ============================
extern "C" void kernel_launch(void* const* d_in, const int* in_sizes, int n_in,
                              void* d_out, int out_size) {
    const float* ent   = (const float*)d_in[0];
    const float* erb   = (const float*)d_in[2];
    const float* onorm = (const float*)d_in[3];
    const float* Wn    = (const float*)d_in[4];
    const float* w_ih  = (const float*)d_in[5];
    const float* w_hh  = (const float*)d_in[6];
    const float* b_ih  = (const float*)d_in[7];
    const float* b_hh  = (const float*)d_in[8];
    const int* node_id = (const int*)d_in[9];
    const int* esrc    = (const int*)d_in[10];
    const int* edst    = (const int*)d_in[11];
    int N = in_sizes[3];
    int E = in_sizes[10];
    float* out = (float*)d_out;
    int npad = ((N + 127) / 128) * 128;
    if (npad > NPAD_MAX) npad = NPAD_MAX;

    cudaFuncSetAttribute(gemm_kernel, cudaFuncAttributeMaxDynamicSharedMemorySize, GEMM_SMEM);

    prep_zero_kernel<<<1025, 256>>>(Wn, w_ih, w_hh, b_ih, b_hh, N);
    int warps_needed = (E + 3) / 4;
    scatter_kernel<<<(warps_needed + 7) / 8, 256>>>(ent, node_id, esrc, edst, E);
    build_x_kernel<<<(npad * 32 + 255) / 256, 256>>>(erb, onorm, N, npad);
    dim3 ggrid(npad / 128, 4);
    gemm_kernel<<<ggrid, 256, GEMM_SMEM>>>(npad);
    epilogue_kernel<<<(N * 32 + 255) / 256, 256>>>(erb, out, N);
}

// round 17
// speedup vs baseline: 1.4260x; 1.1662x over previous
#include <cuda_runtime.h>
#include <cuda_bf16.h>
#include <cuda_fp16.h>
#include <cstdint>
#include <math.h>

#define D 128
#define NMAX 100000
#define NPAD_MAX 100096

// ---- scratch (static device globals; no runtime allocation) ----
static __device__ float g_agg[(size_t)NMAX * D];                // scatter-sum of gathered rows
static __device__ __half g_X[(size_t)NPAD_MAX * 256];           // X (single fp16 term)
static __device__ __half g_B[512 * 256];                        // [n][k] single fp16
static __device__ __half g_C[(size_t)NPAD_MAX * 512];           // GEMM result (fp16 preacts)
static __device__ float g_bias[512];                            // br, bz, bxn, bhh_n

// ============================ PTX helpers (plain sm_103) ============================
__device__ __forceinline__ uint32_t smem_u32(const void* p) {
    uint32_t a;
    asm("{ .reg .u64 t; cvta.to.shared.u64 t, %1; cvt.u32.u64 %0, t; }" : "=r"(a) : "l"(p));
    return a;
}
__device__ __forceinline__ void cp_async16(uint32_t dst, const void* src) {
    asm volatile("cp.async.cg.shared.global [%0], [%1], 16;" :: "r"(dst), "l"(src));
}
__device__ __forceinline__ void ldm_x4(uint32_t* r, uint32_t addr) {
    asm volatile("ldmatrix.sync.aligned.m8n8.x4.shared.b16 {%0,%1,%2,%3}, [%4];"
                 : "=r"(r[0]), "=r"(r[1]), "=r"(r[2]), "=r"(r[3]) : "r"(addr));
}
__device__ __forceinline__ void mma_fp16(float* c, const uint32_t* a, uint32_t b0, uint32_t b1) {
    asm volatile(
        "mma.sync.aligned.m16n8k16.row.col.f32.f16.f16.f32 "
        "{%0,%1,%2,%3}, {%4,%5,%6,%7}, {%8,%9}, {%0,%1,%2,%3};"
        : "+f"(c[0]), "+f"(c[1]), "+f"(c[2]), "+f"(c[3])
        : "r"(a[0]), "r"(a[1]), "r"(a[2]), "r"(a[3]), "r"(b0), "r"(b1));
}
__device__ __forceinline__ float sigmoidf_(float x) { return 1.f / (1.f + expf(-x)); }
// load 4 consecutive fp16 preacts as fp32
__device__ __forceinline__ void ld4h(float* o, const uint2* p) {
    uint2 v = __ldg(p);
    const __half2* h = reinterpret_cast<const __half2*>(&v);
    float2 a = __half22float2(h[0]);
    float2 b = __half22float2(h[1]);
    o[0] = a.x; o[1] = a.y; o[2] = b.x; o[3] = b.y;
}

// ============================ prep + zero (merged) ============================
// Blocks [0,513): weight prep (compute-bound, single fp16). Blocks [513,1025): zero g_agg.
__global__ __launch_bounds__(256) void prep_zero_kernel(
        const float* __restrict__ W, const float* __restrict__ w_ih,
        const float* __restrict__ w_hh, const float* __restrict__ b_ih,
        const float* __restrict__ b_hh, int N) {
    if (blockIdx.x >= 513) {
        size_t total = (size_t)N * 32;
        float4* p = reinterpret_cast<float4*>(g_agg);
        size_t base = ((size_t)blockIdx.x - 513) * blockDim.x + threadIdx.x;
        for (size_t i = base; i < total; i += (size_t)512 * blockDim.x)
            p[i] = make_float4(0.f, 0.f, 0.f, 0.f);
        return;
    }
    int n = blockIdx.x;
    int k = threadIdx.x;
    if (n == 512) {
        if (k < 128) {
            g_bias[k]       = b_ih[k] + b_hh[k];
            g_bias[128 + k] = b_ih[128 + k] + b_hh[128 + k];
            g_bias[256 + k] = b_ih[256 + k];
            g_bias[384 + k] = b_hh[256 + k];
        }
        return;
    }
    float v;
    if (k < 128) {
        if (n < 384) {
            float acc = 0.f;
            for (int j = 0; j < 128; j++) acc = fmaf(W[k * 128 + j], w_ih[n * 256 + j], acc);
            v = acc;
        } else v = 0.f;
    } else {
        if (n < 256)      v = w_ih[n * 256 + k] + w_hh[n * 128 + (k - 128)];
        else if (n < 384) v = w_ih[n * 256 + k];
        else              v = w_hh[(n - 128) * 128 + (k - 128)];
    }
    g_B[n * 256 + k] = __float2half_rn(v);
}

// ============================ scatter (4 edges/warp, direct ent gather) ============================
__global__ __launch_bounds__(256) void scatter_kernel(const float* __restrict__ ent,
                                                      const int* __restrict__ node_id,
                                                      const int* __restrict__ esrc,
                                                      const int* __restrict__ edst, int E) {
    int warp = (int)((blockIdx.x * (size_t)blockDim.x + threadIdx.x) >> 5);
    int lane = threadIdx.x & 31;
    int e0 = warp * 4;
    if (e0 >= E) return;
    int dst[4], row[4];
    #pragma unroll
    for (int j = 0; j < 4; j++) {
        if (e0 + j < E) {
            int s = __ldg(esrc + e0 + j);
            dst[j] = __ldg(edst + e0 + j);
            row[j] = __ldg(node_id + s);
        } else {
            dst[j] = -1; row[j] = 0;
        }
    }
    float4 v[4];
    #pragma unroll
    for (int j = 0; j < 4; j++)
        v[j] = __ldg(reinterpret_cast<const float4*>(ent) + (size_t)row[j] * 32 + lane);
    #pragma unroll
    for (int j = 0; j < 4; j++)
        if (dst[j] >= 0)
            atomicAdd(reinterpret_cast<float4*>(g_agg) + (size_t)dst[j] * 32 + lane, v[j]);
}

// ============================ build X (single fp16) ============================
__global__ __launch_bounds__(256) void build_x_kernel(const float* __restrict__ erb,
                                                      const float* __restrict__ onorm,
                                                      int N, int npad) {
    int i = blockIdx.x * blockDim.x + threadIdx.x;
    int node = i >> 5, lane = i & 31;
    if (node >= npad) return;
    float x[8];
    if (node < N) {
        float sc = __ldg(onorm + node);
        float4 a = __ldg(reinterpret_cast<const float4*>(g_agg) + (size_t)node * 32 + lane);
        float4 e = __ldg(reinterpret_cast<const float4*>(erb) + (size_t)node * 32 + lane);
        x[0] = a.x * sc; x[1] = a.y * sc; x[2] = a.z * sc; x[3] = a.w * sc;
        x[4] = e.x; x[5] = e.y; x[6] = e.z; x[7] = e.w;
    } else {
        #pragma unroll
        for (int q = 0; q < 8; q++) x[q] = 0.f;
    }
    __half2 h01 = __floats2half2_rn(x[0], x[1]);
    __half2 h23 = __floats2half2_rn(x[2], x[3]);
    __half2 h45 = __floats2half2_rn(x[4], x[5]);
    __half2 h67 = __floats2half2_rn(x[6], x[7]);
    *reinterpret_cast<uint2*>(g_X + (size_t)node * 256 + lane * 4) =
        make_uint2(*reinterpret_cast<uint32_t*>(&h01), *reinterpret_cast<uint32_t*>(&h23));
    *reinterpret_cast<uint2*>(g_X + (size_t)node * 256 + 128 + lane * 4) =
        make_uint2(*reinterpret_cast<uint32_t*>(&h45), *reinterpret_cast<uint32_t*>(&h67));
}

// ============================ GEMM: C[npad,512] = X[npad,256] @ B[512,256]^T =========
// K chunks 0-3 (64 wide each). hn gate (d0==384): B rows exactly 0 for k<128 → chunks {2,3}.
// 3-stage cp.async pipeline, one barrier per stage. C stored as fp16.
#define STAGE_BYTES 32768
#define GEMM_SMEM (3 * STAGE_BYTES)

__global__ __launch_bounds__(256, 2) void gemm_kernel(int npad) {
    extern __shared__ char smc[];
    uint32_t sbase = smem_u32(smc);
    int tid = threadIdx.x, lane = tid & 31, w = tid >> 5;
    int n0 = blockIdx.x * 128;
    int d0 = blockIdx.y * 128;
    int wm = w & 3, wn = w >> 2;
    int m0 = wm * 32, nw0 = wn * 64;

    const int map1[2] = {2, 3};
    bool is_hn = (d0 == 384);
    int nch = is_hn ? 2 : 4;

    float acc[2][8][4];
    #pragma unroll
    for (int a = 0; a < 2; a++)
        #pragma unroll
        for (int b = 0; b < 8; b++)
            #pragma unroll
            for (int c = 0; c < 4; c++) acc[a][b][c] = 0.f;

    auto load_chunk = [&](int c, int st) {
        const __half* Asrc = g_X + (size_t)n0 * 256 + c * 64;
        const __half* Bsrc = g_B + (size_t)d0 * 256 + c * 64;
        uint32_t abase = sbase + st * STAGE_BYTES;
        uint32_t bbase = abase + 16384;
        #pragma unroll
        for (int i = 0; i < 4; i++) {
            int e = i * 256 + tid;
            int row = e >> 3, ch = e & 7;
            cp_async16(abase + (row * 8 + (ch ^ (row & 7))) * 16,
                       Asrc + (size_t)row * 256 + ch * 8);
        }
        #pragma unroll
        for (int i = 0; i < 4; i++) {
            int e = i * 256 + tid;
            int row = e >> 3, ch = e & 7;
            cp_async16(bbase + (row * 8 + (ch ^ (row & 7))) * 16,
                       Bsrc + (size_t)row * 256 + ch * 8);
        }
        asm volatile("cp.async.commit_group;" ::: "memory");
    };

    auto chunk_of = [&](int i) { return is_hn ? map1[i] : i; };

    load_chunk(chunk_of(0), 0);
    if (nch > 1) load_chunk(chunk_of(1), 1);

    for (int i = 0; i < nch; i++) {
        int st = i % 3;
        if (i < nch - 1) asm volatile("cp.async.wait_group 1;" ::: "memory");
        else             asm volatile("cp.async.wait_group 0;" ::: "memory");
        __syncthreads();
        // safe: barrier above proves all warps finished reading stage (i+2)%3.
        if (i + 2 < nch) load_chunk(chunk_of(i + 2), (i + 2) % 3);
        uint32_t abase = sbase + st * STAGE_BYTES;
        uint32_t bbase = abase + 16384;
        #pragma unroll
        for (int k16 = 0; k16 < 4; k16++) {
            uint32_t af[2][4], bf[4][4];
            #pragma unroll
            for (int mi = 0; mi < 2; mi++) {
                int row = m0 + mi * 16 + (lane & 15);
                int ch = k16 * 2 + (lane >> 4);
                ldm_x4(af[mi], abase + (row * 8 + (ch ^ (row & 7))) * 16);
            }
            #pragma unroll
            for (int j = 0; j < 4; j++) {
                int row = nw0 + j * 16 + (lane & 15);
                int ch = k16 * 2 + (lane >> 4);
                ldm_x4(bf[j], bbase + (row * 8 + (ch ^ (row & 7))) * 16);
            }
            #pragma unroll
            for (int mi = 0; mi < 2; mi++)
                #pragma unroll
                for (int j = 0; j < 4; j++) {
                    mma_fp16(acc[mi][2 * j],     af[mi], bf[j][0], bf[j][2]);
                    mma_fp16(acc[mi][2 * j + 1], af[mi], bf[j][1], bf[j][3]);
                }
        }
    }

    int tr = lane >> 2, tc = (lane & 3) * 2;
    #pragma unroll
    for (int mi = 0; mi < 2; mi++) {
        #pragma unroll
        for (int j = 0; j < 8; j++) {
            int node = n0 + m0 + mi * 16 + tr;
            int d = d0 + nw0 + j * 8 + tc;
            float* cp = acc[mi][j];
            *reinterpret_cast<__half2*>(g_C + (size_t)node * 512 + d) =
                __floats2half2_rn(cp[0], cp[1]);
            *reinterpret_cast<__half2*>(g_C + (size_t)(node + 8) * 512 + d) =
                __floats2half2_rn(cp[2], cp[3]);
        }
    }
}

// ============================ epilogue: gates + relu + row norm ============================
__global__ __launch_bounds__(256) void epilogue_kernel(const float* __restrict__ erb,
                                                       float* __restrict__ out, int N) {
    int gw = (int)((blockIdx.x * (size_t)blockDim.x + threadIdx.x) >> 5);
    int lane = threadIdx.x & 31;
    if (gw >= N) return;
    const uint2* C2 = reinterpret_cast<const uint2*>(g_C + (size_t)gw * 512);
    float rr[4], zz[4], xx[4], hh[4];
    ld4h(rr, C2 + lane);          // gate r: halves [lane*4 .. lane*4+3]
    ld4h(zz, C2 + 32 + lane);     // gate z
    ld4h(xx, C2 + 64 + lane);     // gate xn
    ld4h(hh, C2 + 96 + lane);     // gate hn
    float4 e4 = __ldg(reinterpret_cast<const float4*>(erb) + (size_t)gw * 32 + lane);
    const float* ee = &e4.x;
    float hv[4];
    float ss = 0.f;
    #pragma unroll
    for (int i = 0; i < 4; i++) {
        int d = lane * 4 + i;
        float r = sigmoidf_(rr[i] + __ldg(g_bias + d));
        float z = sigmoidf_(zz[i] + __ldg(g_bias + 128 + d));
        float nn = tanhf(xx[i] + __ldg(g_bias + 256 + d) + r * (hh[i] + __ldg(g_bias + 384 + d)));
        float h = fmaxf((1.f - z) * nn + z * ee[i], 0.f);
        ss += h * h;
        hv[i] = h;
    }
    #pragma unroll
    for (int o = 16; o; o >>= 1) ss += __shfl_xor_sync(0xFFFFFFFFu, ss, o);
    float inv = 1.f / fmaxf(sqrtf(ss), 1e-12f);
    reinterpret_cast<float4*>(out)[(size_t)gw * 32 + lane] =
        make_float4(hv[0] * inv, hv[1] * inv, hv[2] * inv, hv[3] * inv);
}

// ============================ launch ============================
extern "C" void kernel_launch(void* const* d_in, const int* in_sizes, int n_in,
                              void* d_out, int out_size) {
    const float* ent   = (const float*)d_in[0];
    const float* erb   = (const float*)d_in[2];
    const float* onorm = (const float*)d_in[3];
    const float* Wn    = (const float*)d_in[4];
    const float* w_ih  = (const float*)d_in[5];
    const float* w_hh  = (const float*)d_in[6];
    const float* b_ih  = (const float*)d_in[7];
    const float* b_hh  = (const float*)d_in[8];
    const int* node_id = (const int*)d_in[9];
    const int* esrc    = (const int*)d_in[10];
    const int* edst    = (const int*)d_in[11];
    int N = in_sizes[3];
    int E = in_sizes[10];
    float* out = (float*)d_out;
    int npad = ((N + 127) / 128) * 128;
    if (npad > NPAD_MAX) npad = NPAD_MAX;

    cudaFuncSetAttribute(gemm_kernel, cudaFuncAttributeMaxDynamicSharedMemorySize, GEMM_SMEM);

    prep_zero_kernel<<<1025, 256>>>(Wn, w_ih, w_hh, b_ih, b_hh, N);
    int warps_needed = (E + 3) / 4;
    scatter_kernel<<<(warps_needed + 7) / 8, 256>>>(ent, node_id, esrc, edst, E);
    build_x_kernel<<<(npad * 32 + 255) / 256, 256>>>(erb, onorm, N, npad);
    dim3 ggrid(npad / 128, 4);
    gemm_kernel<<<ggrid, 256, GEMM_SMEM>>>(npad);
    epilogue_kernel<<<(N * 32 + 255) / 256, 256>>>(erb, out, N);
}